// round 13
// baseline (speedup 1.0000x reference)
#include <cuda_runtime.h>
#include <cstdint>

#define NC   200000
#define NF   800000
#define NE   3200000
#define NEP  2400000
#define CIN  128
#define COUT 64
#define XS   132
#define NTILES (NC / 64)
#define NTOT (NC + NF)
#define SCAN_B 1024
#define NSB ((NTOT + SCAN_B - 1) / SCAN_B)   // 977

// Scratch
__device__ float g_h[(size_t)NC * COUT];
__device__ float g_m[(size_t)NC * COUT];
__device__ int   g_cnt[NTOT];
__device__ int   g_off[NTOT];
__device__ int   g_fill[NTOT];
__device__ int   g_part[1024];
__device__ int2  g_epack[NE];    // (src, w-bits) sorted by coarse dst
__device__ int2  g_ppack[NEP];   // (src, w-bits) sorted by fine dst

typedef unsigned long long ull;

__device__ __forceinline__ ull pack2(float a, float b) {
    ull r; asm("mov.b64 %0, {%1, %2};" : "=l"(r) : "f"(a), "f"(b)); return r;
}
__device__ __forceinline__ void ffma2(ull& d, ull a, ull b) {
    asm("fma.rn.f32x2 %0, %1, %2, %3;" : "=l"(d) : "l"(a), "l"(b), "l"(d));
}

// Cache-hinted accessors: .cs = evict-first (streaming), keeps reused rows in L2
__device__ __forceinline__ int2 ldcs_i2(const int2* p) {
    int2 v;
    asm volatile("ld.global.cs.v2.u32 {%0,%1}, [%2];"
                 : "=r"(v.x), "=r"(v.y) : "l"(p));
    return v;
}
__device__ __forceinline__ float4 ldcs_f4(const float* p) {
    float4 v;
    asm volatile("ld.global.cs.v4.f32 {%0,%1,%2,%3}, [%4];"
                 : "=f"(v.x), "=f"(v.y), "=f"(v.z), "=f"(v.w) : "l"(p));
    return v;
}
__device__ __forceinline__ void stcs_f4(float* p, float4 v) {
    asm volatile("st.global.cs.v4.f32 [%0], {%1,%2,%3,%4};"
                 :: "l"(p), "f"(v.x), "f"(v.y), "f"(v.z), "f"(v.w) : "memory");
}

// ---------------------------------------------------------------------------
// K1: fused GEMM h = x @ W_root + b ; m = x @ W_nbr  (R3/R8-proven, 147us)
// ---------------------------------------------------------------------------
__global__ void __launch_bounds__(256, 2)
k_gemm(const float* __restrict__ x,
       const float* __restrict__ Wr,
       const float* __restrict__ Wn,
       const float* __restrict__ bias) {
    extern __shared__ float sm[];
    float* sWr = sm;
    float* sWn = sm + CIN * COUT;
    float* sx  = sm + 2 * CIN * COUT;

    for (int i = threadIdx.x * 4; i < CIN * COUT; i += blockDim.x * 4) {
        *(float4*)&sWr[i] = *(const float4*)&Wr[i];
        *(float4*)&sWn[i] = *(const float4*)&Wn[i];
    }

    const int cg = threadIdx.x & 15;
    const int rg = threadIdx.x >> 4;

    const float4 bv = *(const float4*)&bias[cg * 4];
    const ull bh0 = pack2(bv.x, bv.y);
    const ull bh1 = pack2(bv.z, bv.w);

    for (int tile = blockIdx.x; tile < NTILES; tile += gridDim.x) {
        const int row0 = tile * 64;

        __syncthreads();
        for (int i = threadIdx.x; i < 64 * (CIN / 4); i += blockDim.x) {
            const int r = i >> 5;
            const int c = (i & 31) << 2;
            *(float4*)&sx[r * XS + c] =
                *(const float4*)&x[(size_t)(row0 + r) * CIN + c];
        }
        __syncthreads();

        ull ah[4][2], am[4][2];
#pragma unroll
        for (int j = 0; j < 4; j++) {
            ah[j][0] = bh0; ah[j][1] = bh1;
            am[j][0] = 0ull; am[j][1] = 0ull;
        }

#pragma unroll 2
        for (int k4 = 0; k4 < CIN / 4; k4++) {
            float4 xv[4];
#pragma unroll
            for (int j = 0; j < 4; j++)
                xv[j] = *(const float4*)&sx[(rg * 4 + j) * XS + k4 * 4];

#pragma unroll
            for (int kk = 0; kk < 4; kk++) {
                const int k = k4 * 4 + kk;
                const ulonglong2 wr = *(const ulonglong2*)&sWr[k * COUT + cg * 4];
                const ulonglong2 wn = *(const ulonglong2*)&sWn[k * COUT + cg * 4];
#pragma unroll
                for (int j = 0; j < 4; j++) {
                    const float xs = (kk == 0) ? xv[j].x : (kk == 1) ? xv[j].y
                                   : (kk == 2) ? xv[j].z : xv[j].w;
                    const ull xp = pack2(xs, xs);
                    ffma2(ah[j][0], xp, wr.x);
                    ffma2(ah[j][1], xp, wr.y);
                    ffma2(am[j][0], xp, wn.x);
                    ffma2(am[j][1], xp, wn.y);
                }
            }
        }

#pragma unroll
        for (int j = 0; j < 4; j++) {
            const size_t r = (size_t)(row0 + rg * 4 + j);
            ulonglong2 vh; vh.x = ah[j][0]; vh.y = ah[j][1];
            ulonglong2 vm; vm.x = am[j][0]; vm.y = am[j][1];
            *(ulonglong2*)&g_h[r * COUT + cg * 4] = vh;
            *(ulonglong2*)&g_m[r * COUT + cg * 4] = vm;
        }
    }
}

// ---------------------------------------------------------------------------
// CSR build over BOTH edge sets (unchanged from R8)
// ---------------------------------------------------------------------------
__global__ void k_zero() {
    const int i = blockIdx.x * blockDim.x + threadIdx.x;
    if (i < NTOT) g_cnt[i] = 0;
}

__global__ void k_hist(const int* __restrict__ edst,
                       const int* __restrict__ pdst) {
    const int i = blockIdx.x * blockDim.x + threadIdx.x;
    if (i < NE) {
        atomicAdd(&g_cnt[edst[i]], 1);
    } else if (i < NE + NEP) {
        atomicAdd(&g_cnt[NC + pdst[i - NE]], 1);
    }
}

__global__ void k_scan1() {
    __shared__ int s[256];
    const int tid = threadIdx.x;
    const int base = blockIdx.x * SCAN_B + tid * 4;
    int v[4];
#pragma unroll
    for (int j = 0; j < 4; j++)
        v[j] = (base + j < NTOT) ? g_cnt[base + j] : 0;
    int t = 0;
#pragma unroll
    for (int j = 0; j < 4; j++) { int c = v[j]; v[j] = t; t += c; }
    const int tin = t;
    s[tid] = t;
    __syncthreads();
    for (int d = 1; d < 256; d <<= 1) {
        int y = (tid >= d) ? s[tid - d] : 0;
        __syncthreads();
        s[tid] += y;
        __syncthreads();
    }
    const int ex = s[tid] - tin;
#pragma unroll
    for (int j = 0; j < 4; j++)
        if (base + j < NTOT) g_off[base + j] = ex + v[j];
    if (tid == 255) g_part[blockIdx.x] = s[255];
}

__global__ void k_scan2() {
    __shared__ int s[1024];
    const int tid = threadIdx.x;
    const int t = (tid < NSB) ? g_part[tid] : 0;
    s[tid] = t;
    __syncthreads();
    for (int d = 1; d < 1024; d <<= 1) {
        int y = (tid >= d) ? s[tid - d] : 0;
        __syncthreads();
        s[tid] += y;
        __syncthreads();
    }
    g_part[tid] = s[tid] - t;
}

__global__ void k_scan3() {
    const int i = blockIdx.x * blockDim.x + threadIdx.x;
    if (i < NTOT) {
        const int v = g_off[i] + g_part[i / SCAN_B];
        g_off[i] = v;
        g_fill[i] = v;
    }
}

__global__ void k_fill(const int* __restrict__ esrc,
                       const int* __restrict__ edst,
                       const float* __restrict__ ew,
                       const int* __restrict__ psrc,
                       const int* __restrict__ pdst,
                       const float* __restrict__ pw) {
    const int i = blockIdx.x * blockDim.x + threadIdx.x;
    if (i < NE) {
        const int d = edst[i];
        const int p = atomicAdd(&g_fill[d], 1);
        int2 rec; rec.x = esrc[i]; rec.y = __float_as_int(ew[i]);
        g_epack[p] = rec;
    } else if (i < NE + NEP) {
        const int k = i - NE;
        const int d = pdst[k];
        const int p = atomicAdd(&g_fill[NC + d], 1) - NE;  // coarse total == NE
        int2 rec; rec.x = psrc[k]; rec.y = __float_as_int(pw[k]);
        g_ppack[p] = rec;
    }
}

// ---------------------------------------------------------------------------
// K2: edge gather (8 lanes/node, 2x float4, 4-way unrolled).
// Streaming accesses (.cs): epack records, g_h read/write.
// Reused random rows (g_m, 51MB) get default caching -> stay L2-resident.
// ---------------------------------------------------------------------------
__global__ void k_gather_edge() {
    const long long t = (long long)blockIdx.x * blockDim.x + threadIdx.x;
    const int node = (int)(t >> 3);
    if (node >= NC) return;
    const int c = (int)(t & 7) << 3;

    const int beg = g_off[node];
    const int end = beg + g_cnt[node];

    float4 a0 = make_float4(0.f, 0.f, 0.f, 0.f);
    float4 b0 = make_float4(0.f, 0.f, 0.f, 0.f);
    float4 a1 = make_float4(0.f, 0.f, 0.f, 0.f);
    float4 b1 = make_float4(0.f, 0.f, 0.f, 0.f);

    int j = beg;
    for (; j + 4 <= end; j += 4) {
        const int2 r0 = ldcs_i2(&g_epack[j]);
        const int2 r1 = ldcs_i2(&g_epack[j + 1]);
        const int2 r2 = ldcs_i2(&g_epack[j + 2]);
        const int2 r3 = ldcs_i2(&g_epack[j + 3]);
        const float* p0 = &g_m[(size_t)r0.x * COUT + c];
        const float* p1 = &g_m[(size_t)r1.x * COUT + c];
        const float* p2 = &g_m[(size_t)r2.x * COUT + c];
        const float* p3 = &g_m[(size_t)r3.x * COUT + c];
        const float4 u0a = __ldg((const float4*)p0);
        const float4 u0b = __ldg((const float4*)(p0 + 4));
        const float4 u1a = __ldg((const float4*)p1);
        const float4 u1b = __ldg((const float4*)(p1 + 4));
        const float4 u2a = __ldg((const float4*)p2);
        const float4 u2b = __ldg((const float4*)(p2 + 4));
        const float4 u3a = __ldg((const float4*)p3);
        const float4 u3b = __ldg((const float4*)(p3 + 4));
        const float w0 = __int_as_float(r0.y);
        const float w1 = __int_as_float(r1.y);
        const float w2 = __int_as_float(r2.y);
        const float w3 = __int_as_float(r3.y);
        a0.x = fmaf(u0a.x, w0, a0.x); a0.y = fmaf(u0a.y, w0, a0.y);
        a0.z = fmaf(u0a.z, w0, a0.z); a0.w = fmaf(u0a.w, w0, a0.w);
        b0.x = fmaf(u0b.x, w0, b0.x); b0.y = fmaf(u0b.y, w0, b0.y);
        b0.z = fmaf(u0b.z, w0, b0.z); b0.w = fmaf(u0b.w, w0, b0.w);
        a1.x = fmaf(u1a.x, w1, a1.x); a1.y = fmaf(u1a.y, w1, a1.y);
        a1.z = fmaf(u1a.z, w1, a1.z); a1.w = fmaf(u1a.w, w1, a1.w);
        b1.x = fmaf(u1b.x, w1, b1.x); b1.y = fmaf(u1b.y, w1, b1.y);
        b1.z = fmaf(u1b.z, w1, b1.z); b1.w = fmaf(u1b.w, w1, b1.w);
        a0.x = fmaf(u2a.x, w2, a0.x); a0.y = fmaf(u2a.y, w2, a0.y);
        a0.z = fmaf(u2a.z, w2, a0.z); a0.w = fmaf(u2a.w, w2, a0.w);
        b0.x = fmaf(u2b.x, w2, b0.x); b0.y = fmaf(u2b.y, w2, b0.y);
        b0.z = fmaf(u2b.z, w2, b0.z); b0.w = fmaf(u2b.w, w2, b0.w);
        a1.x = fmaf(u3a.x, w3, a1.x); a1.y = fmaf(u3a.y, w3, a1.y);
        a1.z = fmaf(u3a.z, w3, a1.z); a1.w = fmaf(u3a.w, w3, a1.w);
        b1.x = fmaf(u3b.x, w3, b1.x); b1.y = fmaf(u3b.y, w3, b1.y);
        b1.z = fmaf(u3b.z, w3, b1.z); b1.w = fmaf(u3b.w, w3, b1.w);
    }
    for (; j < end; j++) {
        const int2 r0 = ldcs_i2(&g_epack[j]);
        const float* p0 = &g_m[(size_t)r0.x * COUT + c];
        const float4 u0a = __ldg((const float4*)p0);
        const float4 u0b = __ldg((const float4*)(p0 + 4));
        const float w0 = __int_as_float(r0.y);
        a0.x = fmaf(u0a.x, w0, a0.x); a0.y = fmaf(u0a.y, w0, a0.y);
        a0.z = fmaf(u0a.z, w0, a0.z); a0.w = fmaf(u0a.w, w0, a0.w);
        b0.x = fmaf(u0b.x, w0, b0.x); b0.y = fmaf(u0b.y, w0, b0.y);
        b0.z = fmaf(u0b.z, w0, b0.z); b0.w = fmaf(u0b.w, w0, b0.w);
    }

    float* hp = &g_h[(size_t)node * COUT + c];
    float4 hA = ldcs_f4(hp);           // self term (streamed once)
    float4 hB = ldcs_f4(hp + 4);
    hA.x += a0.x + a1.x; hA.y += a0.y + a1.y;
    hA.z += a0.z + a1.z; hA.w += a0.w + a1.w;
    hB.x += b0.x + b1.x; hB.y += b0.y + b1.y;
    hB.z += b0.z + b1.z; hB.w += b0.w + b1.w;
    stcs_f4(hp, hA);
    stcs_f4(hp + 4, hB);
}

// ---------------------------------------------------------------------------
// K3: pool gather (8 lanes/node, 2x float4, 2-way unrolled).
// Streaming (.cs): ppack records + out writes. Random-reuse g_h via __ldg.
// ---------------------------------------------------------------------------
__global__ void k_gather_pool(float* __restrict__ out) {
    const long long t = (long long)blockIdx.x * blockDim.x + threadIdx.x;
    const int node = (int)(t >> 3);
    if (node >= NF) return;
    const int c = (int)(t & 7) << 3;

    const int beg = g_off[NC + node] - NE;
    const int end = beg + g_cnt[NC + node];

    float4 a0 = make_float4(0.f, 0.f, 0.f, 0.f);
    float4 b0 = make_float4(0.f, 0.f, 0.f, 0.f);
    float4 a1 = make_float4(0.f, 0.f, 0.f, 0.f);
    float4 b1 = make_float4(0.f, 0.f, 0.f, 0.f);

    int j = beg;
    for (; j + 2 <= end; j += 2) {
        const int2 r0 = ldcs_i2(&g_ppack[j]);
        const int2 r1 = ldcs_i2(&g_ppack[j + 1]);
        const float* row0 = &g_h[(size_t)r0.x * COUT + c];
        const float* row1 = &g_h[(size_t)r1.x * COUT + c];
        const float4 u0 = __ldg((const float4*)row0);
        const float4 u1 = __ldg((const float4*)(row0 + 4));
        const float4 v0 = __ldg((const float4*)row1);
        const float4 v1 = __ldg((const float4*)(row1 + 4));
        const float w0 = __int_as_float(r0.y);
        const float w1 = __int_as_float(r1.y);
        a0.x = fmaf(u0.x, w0, a0.x); a0.y = fmaf(u0.y, w0, a0.y);
        a0.z = fmaf(u0.z, w0, a0.z); a0.w = fmaf(u0.w, w0, a0.w);
        b0.x = fmaf(u1.x, w0, b0.x); b0.y = fmaf(u1.y, w0, b0.y);
        b0.z = fmaf(u1.z, w0, b0.z); b0.w = fmaf(u1.w, w0, b0.w);
        a1.x = fmaf(v0.x, w1, a1.x); a1.y = fmaf(v0.y, w1, a1.y);
        a1.z = fmaf(v0.z, w1, a1.z); a1.w = fmaf(v0.w, w1, a1.w);
        b1.x = fmaf(v1.x, w1, b1.x); b1.y = fmaf(v1.y, w1, b1.y);
        b1.z = fmaf(v1.z, w1, b1.z); b1.w = fmaf(v1.w, w1, b1.w);
    }
    if (j < end) {
        const int2 r0 = ldcs_i2(&g_ppack[j]);
        const float* row0 = &g_h[(size_t)r0.x * COUT + c];
        const float4 u0 = __ldg((const float4*)row0);
        const float4 u1 = __ldg((const float4*)(row0 + 4));
        const float w0 = __int_as_float(r0.y);
        a0.x = fmaf(u0.x, w0, a0.x); a0.y = fmaf(u0.y, w0, a0.y);
        a0.z = fmaf(u0.z, w0, a0.z); a0.w = fmaf(u0.w, w0, a0.w);
        b0.x = fmaf(u1.x, w0, b0.x); b0.y = fmaf(u1.y, w0, b0.y);
        b0.z = fmaf(u1.z, w0, b0.z); b0.w = fmaf(u1.w, w0, b0.w);
    }

    float4 accA, accB;
    accA.x = a0.x + a1.x; accA.y = a0.y + a1.y;
    accA.z = a0.z + a1.z; accA.w = a0.w + a1.w;
    accB.x = b0.x + b1.x; accB.y = b0.y + b1.y;
    accB.z = b0.z + b1.z; accB.w = b0.w + b1.w;
    float* o = &out[(size_t)node * COUT + c];
    stcs_f4(o, accA);
    stcs_f4(o + 4, accB);
}

// ---------------------------------------------------------------------------
// Launch: R8 topology (CSR on s2 concurrent with GEMM; join; gathers)
// ---------------------------------------------------------------------------
extern "C" void kernel_launch(void* const* d_in, const int* in_sizes, int n_in,
                              void* d_out, int out_size) {
    const float* x   = (const float*)d_in[0];
    const float* Wr  = (const float*)d_in[1];
    const float* Wn  = (const float*)d_in[2];
    const float* b   = (const float*)d_in[3];
    const int*   ei  = (const int*)d_in[4];
    const float* ea  = (const float*)d_in[5];
    const int*   ps  = (const int*)d_in[6];
    const int*   pd  = (const int*)d_in[7];
    const float* pea = (const float*)d_in[8];
    float*       out = (float*)d_out;

    static cudaStream_t s2 = nullptr;
    static cudaEvent_t evFork = nullptr, evJoin = nullptr;
    if (s2 == nullptr) {
        cudaStreamCreateWithFlags(&s2, cudaStreamNonBlocking);
        cudaEventCreateWithFlags(&evFork, cudaEventDisableTiming);
        cudaEventCreateWithFlags(&evJoin, cudaEventDisableTiming);
        const int smem0 = (2 * CIN * COUT + 64 * XS) * sizeof(float);
        cudaFuncSetAttribute(k_gemm, cudaFuncAttributeMaxDynamicSharedMemorySize, smem0);
    }
    const int smem = (2 * CIN * COUT + 64 * XS) * sizeof(float);

    // Fork: CSR build on s2 (independent of GEMM results)
    cudaEventRecord(evFork, (cudaStream_t)0);
    cudaStreamWaitEvent(s2, evFork, 0);
    k_zero<<<(NTOT + 255) / 256, 256, 0, s2>>>();
    k_hist<<<(NE + NEP + 255) / 256, 256, 0, s2>>>(ei + NE, pd);
    k_scan1<<<NSB, 256, 0, s2>>>();
    k_scan2<<<1, 1024, 0, s2>>>();
    k_scan3<<<(NTOT + 255) / 256, 256, 0, s2>>>();
    k_fill<<<(NE + NEP + 255) / 256, 256, 0, s2>>>(ei, ei + NE, ea, ps, pd, pea);
    cudaEventRecord(evJoin, s2);

    // GEMM on the main stream, concurrent with the build
    k_gemm<<<296, 256, smem>>>(x, Wr, Wn, b);

    // Join
    cudaStreamWaitEvent((cudaStream_t)0, evJoin, 0);

    // Edge aggregation: gather into g_h
    {
        const long long threads = (long long)NC * 8;
        k_gather_edge<<<(int)((threads + 255) / 256), 256>>>();
    }
    // Pool gather (writes every out row exactly once)
    {
        const long long threads = (long long)NF * 8;
        k_gather_pool<<<(int)((threads + 255) / 256), 256>>>(out);
    }
}

// round 15
// speedup vs baseline: 1.2869x; 1.2869x over previous
#include <cuda_runtime.h>
#include <cstdint>

#define NC   200000
#define NF   800000
#define NE   3200000
#define NEP  2400000
#define CIN  128
#define COUT 64
#define XS   132
#define TM   128                              // gemm tile rows
#define NTILES_G ((NC + TM - 1) / TM)         // 1563
#define NTOT (NC + NF)
#define SCAN_B 1024
#define NSB ((NTOT + SCAN_B - 1) / SCAN_B)    // 977

// Scratch
__device__ float g_h[(size_t)NC * COUT];
__device__ float g_m[(size_t)NC * COUT];
__device__ int   g_cnt[NTOT];
__device__ int   g_off[NTOT];
__device__ int   g_fill[NTOT];
__device__ int   g_part[1024];
__device__ int2  g_epack[NE];    // (src, w-bits) sorted by coarse dst
__device__ int2  g_ppack[NEP];   // (src, w-bits) sorted by fine dst

typedef unsigned long long ull;

__device__ __forceinline__ ull pack2(float a, float b) {
    ull r; asm("mov.b64 %0, {%1, %2};" : "=l"(r) : "f"(a), "f"(b)); return r;
}
__device__ __forceinline__ void ffma2(ull& d, ull a, ull b) {
    asm("fma.rn.f32x2 %0, %1, %2, %3;" : "=l"(d) : "l"(a), "l"(b), "l"(d));
}

// ---------------------------------------------------------------------------
// K1: fused GEMM h = x @ W_root + b ; m = x @ W_nbr
// Tile 128 rows x 64 cols, 256 threads, 8 rows x 4 cols per thread.
// 1.0 B/MAC smem traffic (vs 1.5 in the 147us version). 1 CTA/SM (130KB smem).
// ---------------------------------------------------------------------------
__global__ void __launch_bounds__(256, 1)
k_gemm(const float* __restrict__ x,
       const float* __restrict__ Wr,
       const float* __restrict__ Wn,
       const float* __restrict__ bias) {
    extern __shared__ float sm[];
    float* sWr = sm;                    // 8192 floats
    float* sWn = sm + CIN * COUT;       // 8192 floats
    float* sx  = sm + 2 * CIN * COUT;   // 128*132 floats

    for (int i = threadIdx.x * 4; i < CIN * COUT; i += blockDim.x * 4) {
        *(float4*)&sWr[i] = *(const float4*)&Wr[i];
        *(float4*)&sWn[i] = *(const float4*)&Wn[i];
    }

    const int cg = threadIdx.x & 15;    // cols 4*cg..+3
    const int rg = threadIdx.x >> 4;    // rows 8*rg..+7

    const float4 bv = *(const float4*)&bias[cg * 4];
    const ull bh0 = pack2(bv.x, bv.y);
    const ull bh1 = pack2(bv.z, bv.w);

    for (int tile = blockIdx.x; tile < NTILES_G; tile += gridDim.x) {
        const int row0 = tile * TM;

        __syncthreads();
        // stage x tile: 128 rows x 32 float4; 16 float4 per thread
        for (int i = threadIdx.x; i < TM * (CIN / 4); i += blockDim.x) {
            const int r = i >> 5;
            const int c = (i & 31) << 2;
            const int gr = row0 + r;
            float4 v = make_float4(0.f, 0.f, 0.f, 0.f);
            if (gr < NC) v = *(const float4*)&x[(size_t)gr * CIN + c];
            *(float4*)&sx[r * XS + c] = v;
        }
        __syncthreads();

        ull ah[8][2], am[8][2];
#pragma unroll
        for (int j = 0; j < 8; j++) {
            ah[j][0] = bh0; ah[j][1] = bh1;
            am[j][0] = 0ull; am[j][1] = 0ull;
        }

#pragma unroll 2
        for (int k4 = 0; k4 < CIN / 4; k4++) {
            float4 xv[8];
#pragma unroll
            for (int j = 0; j < 8; j++)
                xv[j] = *(const float4*)&sx[(rg * 8 + j) * XS + k4 * 4];

#pragma unroll
            for (int kk = 0; kk < 4; kk++) {
                const int k = k4 * 4 + kk;
                const ulonglong2 wr = *(const ulonglong2*)&sWr[k * COUT + cg * 4];
                const ulonglong2 wn = *(const ulonglong2*)&sWn[k * COUT + cg * 4];
#pragma unroll
                for (int j = 0; j < 8; j++) {
                    const float xs = (kk == 0) ? xv[j].x : (kk == 1) ? xv[j].y
                                   : (kk == 2) ? xv[j].z : xv[j].w;
                    const ull xp = pack2(xs, xs);
                    ffma2(ah[j][0], xp, wr.x);
                    ffma2(ah[j][1], xp, wr.y);
                    ffma2(am[j][0], xp, wn.x);
                    ffma2(am[j][1], xp, wn.y);
                }
            }
        }

#pragma unroll
        for (int j = 0; j < 8; j++) {
            const int r = row0 + rg * 8 + j;
            if (r < NC) {
                ulonglong2 vh; vh.x = ah[j][0]; vh.y = ah[j][1];
                ulonglong2 vm; vm.x = am[j][0]; vm.y = am[j][1];
                *(ulonglong2*)&g_h[(size_t)r * COUT + cg * 4] = vh;
                *(ulonglong2*)&g_m[(size_t)r * COUT + cg * 4] = vm;
            }
        }
    }
}

// ---------------------------------------------------------------------------
// CSR build over BOTH edge sets (R8 verbatim)
// ---------------------------------------------------------------------------
__global__ void k_zero() {
    const int i = blockIdx.x * blockDim.x + threadIdx.x;
    if (i < NTOT) g_cnt[i] = 0;
}

__global__ void k_hist(const int* __restrict__ edst,
                       const int* __restrict__ pdst) {
    const int i = blockIdx.x * blockDim.x + threadIdx.x;
    if (i < NE) {
        atomicAdd(&g_cnt[edst[i]], 1);
    } else if (i < NE + NEP) {
        atomicAdd(&g_cnt[NC + pdst[i - NE]], 1);
    }
}

__global__ void k_scan1() {
    __shared__ int s[256];
    const int tid = threadIdx.x;
    const int base = blockIdx.x * SCAN_B + tid * 4;
    int v[4];
#pragma unroll
    for (int j = 0; j < 4; j++)
        v[j] = (base + j < NTOT) ? g_cnt[base + j] : 0;
    int t = 0;
#pragma unroll
    for (int j = 0; j < 4; j++) { int c = v[j]; v[j] = t; t += c; }
    const int tin = t;
    s[tid] = t;
    __syncthreads();
    for (int d = 1; d < 256; d <<= 1) {
        int y = (tid >= d) ? s[tid - d] : 0;
        __syncthreads();
        s[tid] += y;
        __syncthreads();
    }
    const int ex = s[tid] - tin;
#pragma unroll
    for (int j = 0; j < 4; j++)
        if (base + j < NTOT) g_off[base + j] = ex + v[j];
    if (tid == 255) g_part[blockIdx.x] = s[255];
}

__global__ void k_scan2() {
    __shared__ int s[1024];
    const int tid = threadIdx.x;
    const int t = (tid < NSB) ? g_part[tid] : 0;
    s[tid] = t;
    __syncthreads();
    for (int d = 1; d < 1024; d <<= 1) {
        int y = (tid >= d) ? s[tid - d] : 0;
        __syncthreads();
        s[tid] += y;
        __syncthreads();
    }
    g_part[tid] = s[tid] - t;
}

__global__ void k_scan3() {
    const int i = blockIdx.x * blockDim.x + threadIdx.x;
    if (i < NTOT) {
        const int v = g_off[i] + g_part[i / SCAN_B];
        g_off[i] = v;
        g_fill[i] = v;
    }
}

__global__ void k_fill(const int* __restrict__ esrc,
                       const int* __restrict__ edst,
                       const float* __restrict__ ew,
                       const int* __restrict__ psrc,
                       const int* __restrict__ pdst,
                       const float* __restrict__ pw) {
    const int i = blockIdx.x * blockDim.x + threadIdx.x;
    if (i < NE) {
        const int d = edst[i];
        const int p = atomicAdd(&g_fill[d], 1);
        int2 rec; rec.x = esrc[i]; rec.y = __float_as_int(ew[i]);
        g_epack[p] = rec;
    } else if (i < NE + NEP) {
        const int k = i - NE;
        const int d = pdst[k];
        const int p = atomicAdd(&g_fill[NC + d], 1) - NE;  // coarse total == NE
        int2 rec; rec.x = psrc[k]; rec.y = __float_as_int(pw[k]);
        g_ppack[p] = rec;
    }
}

// ---------------------------------------------------------------------------
// K2: edge gather (8 lanes/node, 2x float4, 4-way unrolled; R8 verbatim)
// ---------------------------------------------------------------------------
__global__ void k_gather_edge() {
    const long long t = (long long)blockIdx.x * blockDim.x + threadIdx.x;
    const int node = (int)(t >> 3);
    if (node >= NC) return;
    const int c = (int)(t & 7) << 3;

    const int beg = g_off[node];
    const int end = beg + g_cnt[node];

    float4 a0 = make_float4(0.f, 0.f, 0.f, 0.f);
    float4 b0 = make_float4(0.f, 0.f, 0.f, 0.f);
    float4 a1 = make_float4(0.f, 0.f, 0.f, 0.f);
    float4 b1 = make_float4(0.f, 0.f, 0.f, 0.f);

    int j = beg;
    for (; j + 4 <= end; j += 4) {
        const int2 r0 = g_epack[j];
        const int2 r1 = g_epack[j + 1];
        const int2 r2 = g_epack[j + 2];
        const int2 r3 = g_epack[j + 3];
        const float* p0 = &g_m[(size_t)r0.x * COUT + c];
        const float* p1 = &g_m[(size_t)r1.x * COUT + c];
        const float* p2 = &g_m[(size_t)r2.x * COUT + c];
        const float* p3 = &g_m[(size_t)r3.x * COUT + c];
        const float4 u0a = *(const float4*)p0;
        const float4 u0b = *(const float4*)(p0 + 4);
        const float4 u1a = *(const float4*)p1;
        const float4 u1b = *(const float4*)(p1 + 4);
        const float4 u2a = *(const float4*)p2;
        const float4 u2b = *(const float4*)(p2 + 4);
        const float4 u3a = *(const float4*)p3;
        const float4 u3b = *(const float4*)(p3 + 4);
        const float w0 = __int_as_float(r0.y);
        const float w1 = __int_as_float(r1.y);
        const float w2 = __int_as_float(r2.y);
        const float w3 = __int_as_float(r3.y);
        a0.x = fmaf(u0a.x, w0, a0.x); a0.y = fmaf(u0a.y, w0, a0.y);
        a0.z = fmaf(u0a.z, w0, a0.z); a0.w = fmaf(u0a.w, w0, a0.w);
        b0.x = fmaf(u0b.x, w0, b0.x); b0.y = fmaf(u0b.y, w0, b0.y);
        b0.z = fmaf(u0b.z, w0, b0.z); b0.w = fmaf(u0b.w, w0, b0.w);
        a1.x = fmaf(u1a.x, w1, a1.x); a1.y = fmaf(u1a.y, w1, a1.y);
        a1.z = fmaf(u1a.z, w1, a1.z); a1.w = fmaf(u1a.w, w1, a1.w);
        b1.x = fmaf(u1b.x, w1, b1.x); b1.y = fmaf(u1b.y, w1, b1.y);
        b1.z = fmaf(u1b.z, w1, b1.z); b1.w = fmaf(u1b.w, w1, b1.w);
        a0.x = fmaf(u2a.x, w2, a0.x); a0.y = fmaf(u2a.y, w2, a0.y);
        a0.z = fmaf(u2a.z, w2, a0.z); a0.w = fmaf(u2a.w, w2, a0.w);
        b0.x = fmaf(u2b.x, w2, b0.x); b0.y = fmaf(u2b.y, w2, b0.y);
        b0.z = fmaf(u2b.z, w2, b0.z); b0.w = fmaf(u2b.w, w2, b0.w);
        a1.x = fmaf(u3a.x, w3, a1.x); a1.y = fmaf(u3a.y, w3, a1.y);
        a1.z = fmaf(u3a.z, w3, a1.z); a1.w = fmaf(u3a.w, w3, a1.w);
        b1.x = fmaf(u3b.x, w3, b1.x); b1.y = fmaf(u3b.y, w3, b1.y);
        b1.z = fmaf(u3b.z, w3, b1.z); b1.w = fmaf(u3b.w, w3, b1.w);
    }
    for (; j < end; j++) {
        const int2 r0 = g_epack[j];
        const float* p0 = &g_m[(size_t)r0.x * COUT + c];
        const float4 u0a = *(const float4*)p0;
        const float4 u0b = *(const float4*)(p0 + 4);
        const float w0 = __int_as_float(r0.y);
        a0.x = fmaf(u0a.x, w0, a0.x); a0.y = fmaf(u0a.y, w0, a0.y);
        a0.z = fmaf(u0a.z, w0, a0.z); a0.w = fmaf(u0a.w, w0, a0.w);
        b0.x = fmaf(u0b.x, w0, b0.x); b0.y = fmaf(u0b.y, w0, b0.y);
        b0.z = fmaf(u0b.z, w0, b0.z); b0.w = fmaf(u0b.w, w0, b0.w);
    }

    float* hp = &g_h[(size_t)node * COUT + c];
    float4 hA = *(const float4*)hp;          // self term
    float4 hB = *(const float4*)(hp + 4);
    hA.x += a0.x + a1.x; hA.y += a0.y + a1.y;
    hA.z += a0.z + a1.z; hA.w += a0.w + a1.w;
    hB.x += b0.x + b1.x; hB.y += b0.y + b1.y;
    hB.z += b0.z + b1.z; hB.w += b0.w + b1.w;
    *(float4*)hp = hA;
    *(float4*)(hp + 4) = hB;
}

// ---------------------------------------------------------------------------
// K3: pool gather (8 lanes/node, 2x float4, 2-way unrolled; R8 verbatim)
// ---------------------------------------------------------------------------
__global__ void k_gather_pool(float* __restrict__ out) {
    const long long t = (long long)blockIdx.x * blockDim.x + threadIdx.x;
    const int node = (int)(t >> 3);
    if (node >= NF) return;
    const int c = (int)(t & 7) << 3;

    const int beg = g_off[NC + node] - NE;
    const int end = beg + g_cnt[NC + node];

    float4 a0 = make_float4(0.f, 0.f, 0.f, 0.f);
    float4 b0 = make_float4(0.f, 0.f, 0.f, 0.f);
    float4 a1 = make_float4(0.f, 0.f, 0.f, 0.f);
    float4 b1 = make_float4(0.f, 0.f, 0.f, 0.f);

    int j = beg;
    for (; j + 2 <= end; j += 2) {
        const int2 r0 = g_ppack[j];
        const int2 r1 = g_ppack[j + 1];
        const float* row0 = &g_h[(size_t)r0.x * COUT + c];
        const float* row1 = &g_h[(size_t)r1.x * COUT + c];
        const float4 u0 = *(const float4*)row0;
        const float4 u1 = *(const float4*)(row0 + 4);
        const float4 v0 = *(const float4*)row1;
        const float4 v1 = *(const float4*)(row1 + 4);
        const float w0 = __int_as_float(r0.y);
        const float w1 = __int_as_float(r1.y);
        a0.x = fmaf(u0.x, w0, a0.x); a0.y = fmaf(u0.y, w0, a0.y);
        a0.z = fmaf(u0.z, w0, a0.z); a0.w = fmaf(u0.w, w0, a0.w);
        b0.x = fmaf(u1.x, w0, b0.x); b0.y = fmaf(u1.y, w0, b0.y);
        b0.z = fmaf(u1.z, w0, b0.z); b0.w = fmaf(u1.w, w0, b0.w);
        a1.x = fmaf(v0.x, w1, a1.x); a1.y = fmaf(v0.y, w1, a1.y);
        a1.z = fmaf(v0.z, w1, a1.z); a1.w = fmaf(v0.w, w1, a1.w);
        b1.x = fmaf(v1.x, w1, b1.x); b1.y = fmaf(v1.y, w1, b1.y);
        b1.z = fmaf(v1.z, w1, b1.z); b1.w = fmaf(v1.w, w1, b1.w);
    }
    if (j < end) {
        const int2 r0 = g_ppack[j];
        const float* row0 = &g_h[(size_t)r0.x * COUT + c];
        const float4 u0 = *(const float4*)row0;
        const float4 u1 = *(const float4*)(row0 + 4);
        const float w0 = __int_as_float(r0.y);
        a0.x = fmaf(u0.x, w0, a0.x); a0.y = fmaf(u0.y, w0, a0.y);
        a0.z = fmaf(u0.z, w0, a0.z); a0.w = fmaf(u0.w, w0, a0.w);
        b0.x = fmaf(u1.x, w0, b0.x); b0.y = fmaf(u1.y, w0, b0.y);
        b0.z = fmaf(u1.z, w0, b0.z); b0.w = fmaf(u1.w, w0, b0.w);
    }

    float4 accA, accB;
    accA.x = a0.x + a1.x; accA.y = a0.y + a1.y;
    accA.z = a0.z + a1.z; accA.w = a0.w + a1.w;
    accB.x = b0.x + b1.x; accB.y = b0.y + b1.y;
    accB.z = b0.z + b1.z; accB.w = b0.w + b1.w;
    float* o = &out[(size_t)node * COUT + c];
    *(float4*)o = accA;
    *(float4*)(o + 4) = accB;
}

// ---------------------------------------------------------------------------
// Launch: R8 topology (CSR on s2 concurrent with GEMM; join; gathers)
// ---------------------------------------------------------------------------
extern "C" void kernel_launch(void* const* d_in, const int* in_sizes, int n_in,
                              void* d_out, int out_size) {
    const float* x   = (const float*)d_in[0];
    const float* Wr  = (const float*)d_in[1];
    const float* Wn  = (const float*)d_in[2];
    const float* b   = (const float*)d_in[3];
    const int*   ei  = (const int*)d_in[4];
    const float* ea  = (const float*)d_in[5];
    const int*   ps  = (const int*)d_in[6];
    const int*   pd  = (const int*)d_in[7];
    const float* pea = (const float*)d_in[8];
    float*       out = (float*)d_out;

    static cudaStream_t s2 = nullptr;
    static cudaEvent_t evFork = nullptr, evJoin = nullptr;
    if (s2 == nullptr) {
        cudaStreamCreateWithFlags(&s2, cudaStreamNonBlocking);
        cudaEventCreateWithFlags(&evFork, cudaEventDisableTiming);
        cudaEventCreateWithFlags(&evJoin, cudaEventDisableTiming);
        const int smem0 = (2 * CIN * COUT + TM * XS) * sizeof(float);
        cudaFuncSetAttribute(k_gemm, cudaFuncAttributeMaxDynamicSharedMemorySize, smem0);
    }
    const int smem = (2 * CIN * COUT + TM * XS) * sizeof(float);  // 133120

    // Fork: CSR build on s2 (independent of GEMM results)
    cudaEventRecord(evFork, (cudaStream_t)0);
    cudaStreamWaitEvent(s2, evFork, 0);
    k_zero<<<(NTOT + 255) / 256, 256, 0, s2>>>();
    k_hist<<<(NE + NEP + 255) / 256, 256, 0, s2>>>(ei + NE, pd);
    k_scan1<<<NSB, 256, 0, s2>>>();
    k_scan2<<<1, 1024, 0, s2>>>();
    k_scan3<<<(NTOT + 255) / 256, 256, 0, s2>>>();
    k_fill<<<(NE + NEP + 255) / 256, 256, 0, s2>>>(ei, ei + NE, ea, ps, pd, pea);
    cudaEventRecord(evJoin, s2);

    // GEMM on the main stream, concurrent with the build
    k_gemm<<<148, 256, smem>>>(x, Wr, Wn, b);

    // Join
    cudaStreamWaitEvent((cudaStream_t)0, evJoin, 0);

    // Edge aggregation: gather into g_h
    {
        const long long threads = (long long)NC * 8;
        k_gather_edge<<<(int)((threads + 255) / 256), 256>>>();
    }
    // Pool gather (writes every out row exactly once)
    {
        const long long threads = (long long)NF * 8;
        k_gather_pool<<<(int)((threads + 255) / 256), 256>>>(out);
    }
}

// round 17
// speedup vs baseline: 1.4395x; 1.1186x over previous
#include <cuda_runtime.h>
#include <cuda_fp16.h>
#include <cstdint>

#define NC   200000
#define NF   800000
#define NE   3200000
#define NEP  2400000
#define CIN  128
#define COUT 64
#define XS   132
#define NTILES (NC / 64)
#define NTOT (NC + NF)
#define SCAN_B 1024
#define NSB ((NTOT + SCAN_B - 1) / SCAN_B)   // 977

// Scratch. g_m is fp16: 25.5MB -> stays L2-resident under streaming traffic.
__device__ float  g_h[(size_t)NC * COUT];
__device__ __half g_m[(size_t)NC * COUT];
__device__ int    g_cnt[NTOT];
__device__ int    g_off[NTOT];
__device__ int    g_fill[NTOT];
__device__ int    g_part[1024];
__device__ int2   g_epack[NE];    // (src, w-bits) sorted by coarse dst
__device__ int2   g_ppack[NEP];   // (src, w-bits) sorted by fine dst

typedef unsigned long long ull;

__device__ __forceinline__ ull pack2(float a, float b) {
    ull r; asm("mov.b64 %0, {%1, %2};" : "=l"(r) : "f"(a), "f"(b)); return r;
}
__device__ __forceinline__ float2 unpk2(ull v) {
    float2 f; asm("mov.b64 {%0, %1}, %2;" : "=f"(f.x), "=f"(f.y) : "l"(v));
    return f;
}
__device__ __forceinline__ void ffma2(ull& d, ull a, ull b) {
    asm("fma.rn.f32x2 %0, %1, %2, %3;" : "=l"(d) : "l"(a), "l"(b), "l"(d));
}

// accumulate 8 fp16 channels (one uint4) * w into two float4 accumulators
__device__ __forceinline__ void acc8(float4& a, float4& b, uint4 q, float w) {
    const float2 f0 = __half22float2(*(__half2*)&q.x);
    const float2 f1 = __half22float2(*(__half2*)&q.y);
    const float2 f2 = __half22float2(*(__half2*)&q.z);
    const float2 f3 = __half22float2(*(__half2*)&q.w);
    a.x = fmaf(f0.x, w, a.x); a.y = fmaf(f0.y, w, a.y);
    a.z = fmaf(f1.x, w, a.z); a.w = fmaf(f1.y, w, a.w);
    b.x = fmaf(f2.x, w, b.x); b.y = fmaf(f2.y, w, b.y);
    b.z = fmaf(f3.x, w, b.z); b.w = fmaf(f3.y, w, b.w);
}

// ---------------------------------------------------------------------------
// K1: fused GEMM h = x @ W_root + b (fp32) ; m = x @ W_nbr (stored fp16)
// R8-proven config: tile 64x64, 256 threads, 4 rows x 4 cols, occ 2.
// ---------------------------------------------------------------------------
__global__ void __launch_bounds__(256, 2)
k_gemm(const float* __restrict__ x,
       const float* __restrict__ Wr,
       const float* __restrict__ Wn,
       const float* __restrict__ bias) {
    extern __shared__ float sm[];
    float* sWr = sm;
    float* sWn = sm + CIN * COUT;
    float* sx  = sm + 2 * CIN * COUT;

    for (int i = threadIdx.x * 4; i < CIN * COUT; i += blockDim.x * 4) {
        *(float4*)&sWr[i] = *(const float4*)&Wr[i];
        *(float4*)&sWn[i] = *(const float4*)&Wn[i];
    }

    const int cg = threadIdx.x & 15;
    const int rg = threadIdx.x >> 4;

    const float4 bv = *(const float4*)&bias[cg * 4];
    const ull bh0 = pack2(bv.x, bv.y);
    const ull bh1 = pack2(bv.z, bv.w);

    for (int tile = blockIdx.x; tile < NTILES; tile += gridDim.x) {
        const int row0 = tile * 64;

        __syncthreads();
        for (int i = threadIdx.x; i < 64 * (CIN / 4); i += blockDim.x) {
            const int r = i >> 5;
            const int c = (i & 31) << 2;
            *(float4*)&sx[r * XS + c] =
                *(const float4*)&x[(size_t)(row0 + r) * CIN + c];
        }
        __syncthreads();

        ull ah[4][2], am[4][2];
#pragma unroll
        for (int j = 0; j < 4; j++) {
            ah[j][0] = bh0; ah[j][1] = bh1;
            am[j][0] = 0ull; am[j][1] = 0ull;
        }

#pragma unroll 2
        for (int k4 = 0; k4 < CIN / 4; k4++) {
            float4 xv[4];
#pragma unroll
            for (int j = 0; j < 4; j++)
                xv[j] = *(const float4*)&sx[(rg * 4 + j) * XS + k4 * 4];

#pragma unroll
            for (int kk = 0; kk < 4; kk++) {
                const int k = k4 * 4 + kk;
                const ulonglong2 wr = *(const ulonglong2*)&sWr[k * COUT + cg * 4];
                const ulonglong2 wn = *(const ulonglong2*)&sWn[k * COUT + cg * 4];
#pragma unroll
                for (int j = 0; j < 4; j++) {
                    const float xs = (kk == 0) ? xv[j].x : (kk == 1) ? xv[j].y
                                   : (kk == 2) ? xv[j].z : xv[j].w;
                    const ull xp = pack2(xs, xs);
                    ffma2(ah[j][0], xp, wr.x);
                    ffma2(ah[j][1], xp, wr.y);
                    ffma2(am[j][0], xp, wn.x);
                    ffma2(am[j][1], xp, wn.y);
                }
            }
        }

#pragma unroll
        for (int j = 0; j < 4; j++) {
            const size_t r = (size_t)(row0 + rg * 4 + j);
            ulonglong2 vh; vh.x = ah[j][0]; vh.y = ah[j][1];
            *(ulonglong2*)&g_h[r * COUT + cg * 4] = vh;
            // m -> fp16 (4 halves = 8 bytes)
            const __half2 m0 = __float22half2_rn(unpk2(am[j][0]));
            const __half2 m1 = __float22half2_rn(unpk2(am[j][1]));
            uint2 vm; vm.x = *(const uint32_t*)&m0; vm.y = *(const uint32_t*)&m1;
            *(uint2*)&g_m[r * COUT + cg * 4] = vm;
        }
    }
}

// ---------------------------------------------------------------------------
// CSR build over BOTH edge sets (R8 verbatim)
// ---------------------------------------------------------------------------
__global__ void k_zero() {
    const int i = blockIdx.x * blockDim.x + threadIdx.x;
    if (i < NTOT) g_cnt[i] = 0;
}

__global__ void k_hist(const int* __restrict__ edst,
                       const int* __restrict__ pdst) {
    const int i = blockIdx.x * blockDim.x + threadIdx.x;
    if (i < NE) {
        atomicAdd(&g_cnt[edst[i]], 1);
    } else if (i < NE + NEP) {
        atomicAdd(&g_cnt[NC + pdst[i - NE]], 1);
    }
}

__global__ void k_scan1() {
    __shared__ int s[256];
    const int tid = threadIdx.x;
    const int base = blockIdx.x * SCAN_B + tid * 4;
    int v[4];
#pragma unroll
    for (int j = 0; j < 4; j++)
        v[j] = (base + j < NTOT) ? g_cnt[base + j] : 0;
    int t = 0;
#pragma unroll
    for (int j = 0; j < 4; j++) { int c = v[j]; v[j] = t; t += c; }
    const int tin = t;
    s[tid] = t;
    __syncthreads();
    for (int d = 1; d < 256; d <<= 1) {
        int y = (tid >= d) ? s[tid - d] : 0;
        __syncthreads();
        s[tid] += y;
        __syncthreads();
    }
    const int ex = s[tid] - tin;
#pragma unroll
    for (int j = 0; j < 4; j++)
        if (base + j < NTOT) g_off[base + j] = ex + v[j];
    if (tid == 255) g_part[blockIdx.x] = s[255];
}

__global__ void k_scan2() {
    __shared__ int s[1024];
    const int tid = threadIdx.x;
    const int t = (tid < NSB) ? g_part[tid] : 0;
    s[tid] = t;
    __syncthreads();
    for (int d = 1; d < 1024; d <<= 1) {
        int y = (tid >= d) ? s[tid - d] : 0;
        __syncthreads();
        s[tid] += y;
        __syncthreads();
    }
    g_part[tid] = s[tid] - t;
}

__global__ void k_scan3() {
    const int i = blockIdx.x * blockDim.x + threadIdx.x;
    if (i < NTOT) {
        const int v = g_off[i] + g_part[i / SCAN_B];
        g_off[i] = v;
        g_fill[i] = v;
    }
}

__global__ void k_fill(const int* __restrict__ esrc,
                       const int* __restrict__ edst,
                       const float* __restrict__ ew,
                       const int* __restrict__ psrc,
                       const int* __restrict__ pdst,
                       const float* __restrict__ pw) {
    const int i = blockIdx.x * blockDim.x + threadIdx.x;
    if (i < NE) {
        const int d = edst[i];
        const int p = atomicAdd(&g_fill[d], 1);
        int2 rec; rec.x = esrc[i]; rec.y = __float_as_int(ew[i]);
        g_epack[p] = rec;
    } else if (i < NE + NEP) {
        const int k = i - NE;
        const int d = pdst[k];
        const int p = atomicAdd(&g_fill[NC + d], 1) - NE;  // coarse total == NE
        int2 rec; rec.x = psrc[k]; rec.y = __float_as_int(pw[k]);
        g_ppack[p] = rec;
    }
}

// ---------------------------------------------------------------------------
// K2: edge gather. 8 lanes/node, 8 channels (one uint4 of fp16) per lane,
// 4-way unrolled. Reads fp16 g_m (L2-resident), fp32 self term in g_h.
// ---------------------------------------------------------------------------
__global__ void k_gather_edge() {
    const long long t = (long long)blockIdx.x * blockDim.x + threadIdx.x;
    const int node = (int)(t >> 3);
    if (node >= NC) return;
    const int c = (int)(t & 7) << 3;   // 8 consecutive channels

    const int beg = g_off[node];
    const int end = beg + g_cnt[node];

    float4 a0 = make_float4(0.f, 0.f, 0.f, 0.f);
    float4 b0 = make_float4(0.f, 0.f, 0.f, 0.f);
    float4 a1 = make_float4(0.f, 0.f, 0.f, 0.f);
    float4 b1 = make_float4(0.f, 0.f, 0.f, 0.f);

    int j = beg;
    for (; j + 4 <= end; j += 4) {
        const int2 r0 = g_epack[j];
        const int2 r1 = g_epack[j + 1];
        const int2 r2 = g_epack[j + 2];
        const int2 r3 = g_epack[j + 3];
        const uint4 q0 = *(const uint4*)&g_m[(size_t)r0.x * COUT + c];
        const uint4 q1 = *(const uint4*)&g_m[(size_t)r1.x * COUT + c];
        const uint4 q2 = *(const uint4*)&g_m[(size_t)r2.x * COUT + c];
        const uint4 q3 = *(const uint4*)&g_m[(size_t)r3.x * COUT + c];
        acc8(a0, b0, q0, __int_as_float(r0.y));
        acc8(a1, b1, q1, __int_as_float(r1.y));
        acc8(a0, b0, q2, __int_as_float(r2.y));
        acc8(a1, b1, q3, __int_as_float(r3.y));
    }
    for (; j < end; j++) {
        const int2 r0 = g_epack[j];
        const uint4 q0 = *(const uint4*)&g_m[(size_t)r0.x * COUT + c];
        acc8(a0, b0, q0, __int_as_float(r0.y));
    }

    float* hp = &g_h[(size_t)node * COUT + c];
    float4 hA = *(const float4*)hp;          // self term
    float4 hB = *(const float4*)(hp + 4);
    hA.x += a0.x + a1.x; hA.y += a0.y + a1.y;
    hA.z += a0.z + a1.z; hA.w += a0.w + a1.w;
    hB.x += b0.x + b1.x; hB.y += b0.y + b1.y;
    hB.z += b0.z + b1.z; hB.w += b0.w + b1.w;
    *(float4*)hp = hA;
    *(float4*)(hp + 4) = hB;
}

// ---------------------------------------------------------------------------
// K3: pool gather (8 lanes/node, 2x float4, 2-way unrolled; R8 verbatim)
// ---------------------------------------------------------------------------
__global__ void k_gather_pool(float* __restrict__ out) {
    const long long t = (long long)blockIdx.x * blockDim.x + threadIdx.x;
    const int node = (int)(t >> 3);
    if (node >= NF) return;
    const int c = (int)(t & 7) << 3;

    const int beg = g_off[NC + node] - NE;
    const int end = beg + g_cnt[NC + node];

    float4 a0 = make_float4(0.f, 0.f, 0.f, 0.f);
    float4 b0 = make_float4(0.f, 0.f, 0.f, 0.f);
    float4 a1 = make_float4(0.f, 0.f, 0.f, 0.f);
    float4 b1 = make_float4(0.f, 0.f, 0.f, 0.f);

    int j = beg;
    for (; j + 2 <= end; j += 2) {
        const int2 r0 = g_ppack[j];
        const int2 r1 = g_ppack[j + 1];
        const float* row0 = &g_h[(size_t)r0.x * COUT + c];
        const float* row1 = &g_h[(size_t)r1.x * COUT + c];
        const float4 u0 = *(const float4*)row0;
        const float4 u1 = *(const float4*)(row0 + 4);
        const float4 v0 = *(const float4*)row1;
        const float4 v1 = *(const float4*)(row1 + 4);
        const float w0 = __int_as_float(r0.y);
        const float w1 = __int_as_float(r1.y);
        a0.x = fmaf(u0.x, w0, a0.x); a0.y = fmaf(u0.y, w0, a0.y);
        a0.z = fmaf(u0.z, w0, a0.z); a0.w = fmaf(u0.w, w0, a0.w);
        b0.x = fmaf(u1.x, w0, b0.x); b0.y = fmaf(u1.y, w0, b0.y);
        b0.z = fmaf(u1.z, w0, b0.z); b0.w = fmaf(u1.w, w0, b0.w);
        a1.x = fmaf(v0.x, w1, a1.x); a1.y = fmaf(v0.y, w1, a1.y);
        a1.z = fmaf(v0.z, w1, a1.z); a1.w = fmaf(v0.w, w1, a1.w);
        b1.x = fmaf(v1.x, w1, b1.x); b1.y = fmaf(v1.y, w1, b1.y);
        b1.z = fmaf(v1.z, w1, b1.z); b1.w = fmaf(v1.w, w1, b1.w);
    }
    if (j < end) {
        const int2 r0 = g_ppack[j];
        const float* row0 = &g_h[(size_t)r0.x * COUT + c];
        const float4 u0 = *(const float4*)row0;
        const float4 u1 = *(const float4*)(row0 + 4);
        const float w0 = __int_as_float(r0.y);
        a0.x = fmaf(u0.x, w0, a0.x); a0.y = fmaf(u0.y, w0, a0.y);
        a0.z = fmaf(u0.z, w0, a0.z); a0.w = fmaf(u0.w, w0, a0.w);
        b0.x = fmaf(u1.x, w0, b0.x); b0.y = fmaf(u1.y, w0, b0.y);
        b0.z = fmaf(u1.z, w0, b0.z); b0.w = fmaf(u1.w, w0, b0.w);
    }

    float4 accA, accB;
    accA.x = a0.x + a1.x; accA.y = a0.y + a1.y;
    accA.z = a0.z + a1.z; accA.w = a0.w + a1.w;
    accB.x = b0.x + b1.x; accB.y = b0.y + b1.y;
    accB.z = b0.z + b1.z; accB.w = b0.w + b1.w;
    float* o = &out[(size_t)node * COUT + c];
    *(float4*)o = accA;
    *(float4*)(o + 4) = accB;
}

// ---------------------------------------------------------------------------
// Launch: R8 topology (CSR on s2 concurrent with GEMM; join; gathers)
// ---------------------------------------------------------------------------
extern "C" void kernel_launch(void* const* d_in, const int* in_sizes, int n_in,
                              void* d_out, int out_size) {
    const float* x   = (const float*)d_in[0];
    const float* Wr  = (const float*)d_in[1];
    const float* Wn  = (const float*)d_in[2];
    const float* b   = (const float*)d_in[3];
    const int*   ei  = (const int*)d_in[4];
    const float* ea  = (const float*)d_in[5];
    const int*   ps  = (const int*)d_in[6];
    const int*   pd  = (const int*)d_in[7];
    const float* pea = (const float*)d_in[8];
    float*       out = (float*)d_out;

    static cudaStream_t s2 = nullptr;
    static cudaEvent_t evFork = nullptr, evJoin = nullptr;
    if (s2 == nullptr) {
        cudaStreamCreateWithFlags(&s2, cudaStreamNonBlocking);
        cudaEventCreateWithFlags(&evFork, cudaEventDisableTiming);
        cudaEventCreateWithFlags(&evJoin, cudaEventDisableTiming);
        const int smem0 = (2 * CIN * COUT + 64 * XS) * sizeof(float);
        cudaFuncSetAttribute(k_gemm, cudaFuncAttributeMaxDynamicSharedMemorySize, smem0);
    }
    const int smem = (2 * CIN * COUT + 64 * XS) * sizeof(float);  // 99328

    // Fork: CSR build on s2 (independent of GEMM results)
    cudaEventRecord(evFork, (cudaStream_t)0);
    cudaStreamWaitEvent(s2, evFork, 0);
    k_zero<<<(NTOT + 255) / 256, 256, 0, s2>>>();
    k_hist<<<(NE + NEP + 255) / 256, 256, 0, s2>>>(ei + NE, pd);
    k_scan1<<<NSB, 256, 0, s2>>>();
    k_scan2<<<1, 1024, 0, s2>>>();
    k_scan3<<<(NTOT + 255) / 256, 256, 0, s2>>>();
    k_fill<<<(NE + NEP + 255) / 256, 256, 0, s2>>>(ei, ei + NE, ea, ps, pd, pea);
    cudaEventRecord(evJoin, s2);

    // GEMM on the main stream, concurrent with the build
    k_gemm<<<296, 256, smem>>>(x, Wr, Wn, b);

    // Join
    cudaStreamWaitEvent((cudaStream_t)0, evJoin, 0);

    // Edge aggregation: gather into g_h
    {
        const long long threads = (long long)NC * 8;
        k_gather_edge<<<(int)((threads + 255) / 256), 256>>>();
    }
    // Pool gather (writes every out row exactly once)
    {
        const long long threads = (long long)NF * 8;
        k_gather_pool<<<(int)((threads + 255) / 256), 256>>>(out);
    }
}